// round 1
// baseline (speedup 1.0000x reference)
#include <cuda_runtime.h>
#include <math.h>

#define Nn_NODES 65536
#define Dd 1024
#define Ss 512
#define Kk_SLOTS 64
#define NPAD 128            // padded slot dim for GEMM-able logits
#define AGG_BLOCKS 256
#define AGG_ROWS (Nn_NODES / AGG_BLOCKS)   // 256

// ---------------- scratch (static device globals; no allocations) ------------
__device__ float g_KpT[Ss * NPAD];            // Kp^T padded  [512,128]
__device__ float g_stateT[Ss * NPAD];         // state^T padded [512,128]
__device__ float g_V[Kk_SLOTS * Ss];          // [64,512]
__device__ float g_Q[(size_t)Nn_NODES * Ss];          // [N,512]
__device__ float g_logits[(size_t)Nn_NODES * NPAD];   // [N,128]
__device__ float g_attn[(size_t)Nn_NODES * Kk_SLOTS]; // [N,64]
__device__ float g_read[(size_t)Nn_NODES * Ss];       // [N,512]
__device__ float g_ro[(size_t)Nn_NODES * Dd];         // [N,1024]
__device__ float g_A1[(size_t)Nn_NODES * Ss];         // [N,512]
__device__ float g_erase[(size_t)Nn_NODES * Ss];      // [N,512]
__device__ float g_content[(size_t)Nn_NODES * Ss];    // [N,512]
__device__ float g_weighted[(size_t)Nn_NODES * Kk_SLOTS]; // [N,64]
__device__ float g_gate[Nn_NODES];
__device__ float g_partE[(size_t)AGG_BLOCKS * Kk_SLOTS * Ss]; // [256,64*512]
__device__ float g_partW[(size_t)AGG_BLOCKS * Kk_SLOTS * Ss];

// ---------------- small setup kernels ----------------------------------------
__global__ void zero_pad_kernel() {
    int i = blockIdx.x * blockDim.x + threadIdx.x;
    if (i < Ss * NPAD) { g_KpT[i] = 0.f; g_stateT[i] = 0.f; }
}

// Kp = state@Wk (stored transposed+padded), V = state@Wv, stateT padded
__global__ void kv_kernel(const float* __restrict__ state,
                          const float* __restrict__ Wk,
                          const float* __restrict__ Wv) {
    int j = blockIdx.x; // slot 0..63
    __shared__ float srow[Ss];
    for (int c = threadIdx.x; c < Ss; c += blockDim.x) srow[c] = state[j * Ss + c];
    __syncthreads();
    for (int c = threadIdx.x; c < Ss; c += blockDim.x) {
        float ak = 0.f, av = 0.f;
        for (int t = 0; t < Ss; t++) {
            float s = srow[t];
            ak += s * Wk[t * Ss + c];
            av += s * Wv[t * Ss + c];
        }
        g_KpT[c * NPAD + j] = ak;
        g_V[j * Ss + c] = av;
        g_stateT[c * NPAD + j] = srow[c];
    }
}

// ---------------- generic tiled SGEMM  C[M,n] = act(A[M,k] @ B[k,n]) ----------
// ACT: 0 none, 1 *scale, 2 sigmoid(x+bias[col]), 3 tanh(x+bias[col])
template <int ACT>
__global__ void __launch_bounds__(256)
sgemm128(const float* __restrict__ A, const float* __restrict__ B,
         float* __restrict__ C, int M, int Nc, int Kd,
         const float* __restrict__ bias, float scale) {
    __shared__ float As[8][128];
    __shared__ float Bs[8][128];
    int tid = threadIdx.x;
    int row0 = blockIdx.y * 128, col0 = blockIdx.x * 128;
    int tx = tid & 15, ty = tid >> 4;

    float acc[8][8];
#pragma unroll
    for (int i = 0; i < 8; i++)
#pragma unroll
        for (int j = 0; j < 8; j++) acc[i][j] = 0.f;

    int aRow = tid >> 1, aCol = (tid & 1) * 4;
    int bRow = tid >> 5, bCol = (tid & 31) * 4;
    const float* Aptr = A + (size_t)(row0 + aRow) * Kd + aCol;
    const float* Bptr = B + (size_t)bRow * Nc + col0 + bCol;

    for (int k0 = 0; k0 < Kd; k0 += 8) {
        float4 a4 = *(const float4*)(Aptr + k0);
        float4 b4 = *(const float4*)(Bptr + (size_t)k0 * Nc);
        As[aCol + 0][aRow] = a4.x;
        As[aCol + 1][aRow] = a4.y;
        As[aCol + 2][aRow] = a4.z;
        As[aCol + 3][aRow] = a4.w;
        *(float4*)&Bs[bRow][bCol] = b4;
        __syncthreads();
#pragma unroll
        for (int kk = 0; kk < 8; kk++) {
            float ra[8], rb[8];
            *(float4*)(ra)     = *(const float4*)&As[kk][ty * 8];
            *(float4*)(ra + 4) = *(const float4*)&As[kk][ty * 8 + 4];
            *(float4*)(rb)     = *(const float4*)&Bs[kk][tx * 8];
            *(float4*)(rb + 4) = *(const float4*)&Bs[kk][tx * 8 + 4];
#pragma unroll
            for (int i = 0; i < 8; i++)
#pragma unroll
                for (int j = 0; j < 8; j++) acc[i][j] += ra[i] * rb[j];
        }
        __syncthreads();
    }

#pragma unroll
    for (int i = 0; i < 8; i++) {
        int r = row0 + ty * 8 + i;
#pragma unroll
        for (int j0 = 0; j0 < 8; j0 += 4) {
            float4 o;
            float v[4];
#pragma unroll
            for (int j = 0; j < 4; j++) {
                int col = col0 + tx * 8 + j0 + j;
                float x = acc[i][j0 + j];
                if (ACT == 1) x *= scale;
                if (ACT == 2) x = 1.f / (1.f + __expf(-(x + bias[col])));
                if (ACT == 3) x = tanhf(x + bias[col]);
                v[j] = x;
            }
            o.x = v[0]; o.y = v[1]; o.z = v[2]; o.w = v[3];
            *(float4*)&C[(size_t)r * Nc + col0 + tx * 8 + j0] = o;
        }
    }
}

// ---------------- softmax over 64 slots (optionally * gate) -------------------
__global__ void softmax_kernel(const float* __restrict__ logits,
                               const float* __restrict__ gate,
                               float* __restrict__ out) {
    int row = blockIdx.x * blockDim.y + threadIdx.y;
    int lane = threadIdx.x;
    float v0 = logits[(size_t)row * NPAD + lane];
    float v1 = logits[(size_t)row * NPAD + 32 + lane];
    float m = fmaxf(v0, v1);
#pragma unroll
    for (int o = 16; o; o >>= 1) m = fmaxf(m, __shfl_xor_sync(0xffffffffu, m, o));
    float e0 = __expf(v0 - m), e1 = __expf(v1 - m);
    float s = e0 + e1;
#pragma unroll
    for (int o = 16; o; o >>= 1) s += __shfl_xor_sync(0xffffffffu, s, o);
    float inv = 1.f / s;
    if (gate) inv *= gate[row];
    out[(size_t)row * 64 + lane] = e0 * inv;
    out[(size_t)row * 64 + 32 + lane] = e1 * inv;
}

// ---------------- LayerNorm(x+ro) + gate dot ---------------------------------
__global__ void ln_gate_kernel(const float* __restrict__ nf,
                               const float* __restrict__ ro,
                               const float* __restrict__ gamma,
                               const float* __restrict__ beta,
                               const float* __restrict__ Wg,
                               const float* __restrict__ bg,
                               float* __restrict__ h,
                               float* __restrict__ gate) {
    int row = blockIdx.x;
    int tid = threadIdx.x; // 256 threads, 4 elems each
    __shared__ float sh[16];
    float4 a = ((const float4*)(nf + (size_t)row * Dd))[tid];
    float4 b = ((const float4*)(ro + (size_t)row * Dd))[tid];
    float v0 = a.x + b.x, v1 = a.y + b.y, v2 = a.z + b.z, v3 = a.w + b.w;
    float s = v0 + v1 + v2 + v3;
    float sq = v0 * v0 + v1 * v1 + v2 * v2 + v3 * v3;
    int lane = tid & 31, wid = tid >> 5;
#pragma unroll
    for (int o = 16; o; o >>= 1) {
        s += __shfl_xor_sync(0xffffffffu, s, o);
        sq += __shfl_xor_sync(0xffffffffu, sq, o);
    }
    if (lane == 0) { sh[wid] = s; sh[8 + wid] = sq; }
    __syncthreads();
    if (tid < 32) {
        float rs = (lane < 8) ? sh[lane] : 0.f;
        float rq = (lane < 8) ? sh[8 + lane] : 0.f;
#pragma unroll
        for (int o = 4; o; o >>= 1) {
            rs += __shfl_xor_sync(0xffffffffu, rs, o);
            rq += __shfl_xor_sync(0xffffffffu, rq, o);
        }
        if (lane == 0) { sh[0] = rs; sh[1] = rq; }
    }
    __syncthreads();
    float mu = sh[0] * (1.f / Dd);
    float var = sh[1] * (1.f / Dd) - mu * mu;
    float inv = rsqrtf(var + 1e-6f);
    __syncthreads();

    float4 g4 = ((const float4*)gamma)[tid];
    float4 b4 = ((const float4*)beta)[tid];
    float h0 = (v0 - mu) * inv * g4.x + b4.x;
    float h1 = (v1 - mu) * inv * g4.y + b4.y;
    float h2 = (v2 - mu) * inv * g4.z + b4.z;
    float h3 = (v3 - mu) * inv * g4.w + b4.w;
    float4 o4; o4.x = h0; o4.y = h1; o4.z = h2; o4.w = h3;
    ((float4*)(h + (size_t)row * Dd))[tid] = o4;

    float4 w4 = ((const float4*)Wg)[tid];
    float gd = h0 * w4.x + h1 * w4.y + h2 * w4.z + h3 * w4.w;
#pragma unroll
    for (int o = 16; o; o >>= 1) gd += __shfl_xor_sync(0xffffffffu, gd, o);
    if (lane == 0) sh[wid] = gd;
    __syncthreads();
    if (tid == 0) {
        float t = 0.f;
#pragma unroll
        for (int w = 0; w < 8; w++) t += sh[w];
        gate[row] = 1.f / (1.f + __expf(-(t + bg[0])));
    }
}

// ---------------- partial aggregation: part[blk] = W_chunk^T @ vec_chunk ------
__global__ void __launch_bounds__(512)
aggregate_kernel(const float* __restrict__ w, const float* __restrict__ vec,
                 float* __restrict__ part) {
    int blk = blockIdx.x;
    int tid = threadIdx.x;
    int j = tid >> 3;      // 0..63
    int sb = tid & 7;      // 0..7
    float acc[64];
#pragma unroll
    for (int t = 0; t < 64; t++) acc[t] = 0.f;
    __shared__ float ws[64];
    __shared__ float vs[Ss];
    int r0 = blk * AGG_ROWS;
    for (int r = 0; r < AGG_ROWS; r++) {
        size_t row = r0 + r;
        __syncthreads();
        if (tid < 64) ws[tid] = w[row * 64 + tid];
        if (tid < 512) vs[tid] = vec[row * Ss + tid];
        __syncthreads();
        float wv = ws[j];
#pragma unroll
        for (int t = 0; t < 64; t++) acc[t] += wv * vs[sb + 8 * t];
    }
    float* p = part + (size_t)blk * (Kk_SLOTS * Ss) + j * Ss;
#pragma unroll
    for (int t = 0; t < 64; t++) p[sb + 8 * t] = acc[t];
}

// ---------------- finalize: reduce partials, clip erase, update state ---------
__global__ void finalize_kernel(const float* __restrict__ state,
                                float* __restrict__ out) {
    int e = blockIdx.x * blockDim.x + threadIdx.x;
    if (e >= Kk_SLOTS * Ss) return;
    float se = 0.f, sw = 0.f;
    for (int r = 0; r < AGG_BLOCKS; r++) {
        se += g_partE[(size_t)r * (Kk_SLOTS * Ss) + e];
        sw += g_partW[(size_t)r * (Kk_SLOTS * Ss) + e];
    }
    float ea = fminf(fmaxf(se, 0.f), 1.f);
    out[e] = state[e] * (1.f - ea) + sw;
}

// ---------------- launcher ----------------------------------------------------
extern "C" void kernel_launch(void* const* d_in, const int* in_sizes, int n_in,
                              void* d_out, int out_size) {
    const float* nf    = (const float*)d_in[0];
    const float* state = (const float*)d_in[1];
    const float* Wq    = (const float*)d_in[2];
    const float* Wk    = (const float*)d_in[3];
    const float* Wv    = (const float*)d_in[4];
    const float* Wo    = (const float*)d_in[5];
    const float* gam   = (const float*)d_in[6];
    const float* bet   = (const float*)d_in[7];
    const float* Wa    = (const float*)d_in[8];
    const float* Wg    = (const float*)d_in[9];
    const float* bg    = (const float*)d_in[10];
    const float* We    = (const float*)d_in[11];
    const float* be    = (const float*)d_in[12];
    const float* Wc    = (const float*)d_in[13];
    const float* bc    = (const float*)d_in[14];

    float* h_out = (float*)d_out;                       // [N, D]
    float* ns_out = (float*)d_out + (size_t)Nn_NODES * Dd; // [K, S]

    float *pQ, *pKpT, *pStT, *pV, *pLog, *pAttn, *pRead, *pRo, *pA1;
    float *pEr, *pCo, *pWt, *pGate;
    cudaGetSymbolAddress((void**)&pQ, g_Q);
    cudaGetSymbolAddress((void**)&pKpT, g_KpT);
    cudaGetSymbolAddress((void**)&pStT, g_stateT);
    cudaGetSymbolAddress((void**)&pV, g_V);
    cudaGetSymbolAddress((void**)&pLog, g_logits);
    cudaGetSymbolAddress((void**)&pAttn, g_attn);
    cudaGetSymbolAddress((void**)&pRead, g_read);
    cudaGetSymbolAddress((void**)&pRo, g_ro);
    cudaGetSymbolAddress((void**)&pA1, g_A1);
    cudaGetSymbolAddress((void**)&pEr, g_erase);
    cudaGetSymbolAddress((void**)&pCo, g_content);
    cudaGetSymbolAddress((void**)&pWt, g_weighted);
    cudaGetSymbolAddress((void**)&pGate, g_gate);
    float* pPE; float* pPW;
    cudaGetSymbolAddress((void**)&pPE, g_partE);
    cudaGetSymbolAddress((void**)&pPW, g_partW);

    const float scale = 0.044194173824159216f; // 1/sqrt(512)

    // setup
    zero_pad_kernel<<<(Ss * NPAD + 255) / 256, 256>>>();
    kv_kernel<<<Kk_SLOTS, 256>>>(state, Wk, Wv);

    // read path
    sgemm128<0><<<dim3(Ss / 128, Nn_NODES / 128), 256>>>(nf, Wq, pQ, Nn_NODES, Ss, Dd, nullptr, 0.f);
    sgemm128<1><<<dim3(NPAD / 128, Nn_NODES / 128), 256>>>(pQ, pKpT, pLog, Nn_NODES, NPAD, Ss, nullptr, scale);
    softmax_kernel<<<Nn_NODES / 8, dim3(32, 8)>>>(pLog, nullptr, pAttn);
    sgemm128<0><<<dim3(Ss / 128, Nn_NODES / 128), 256>>>(pAttn, pV, pRead, Nn_NODES, Ss, Kk_SLOTS, nullptr, 0.f);
    sgemm128<0><<<dim3(Dd / 128, Nn_NODES / 128), 256>>>(pRead, Wo, pRo, Nn_NODES, Dd, Ss, nullptr, 0.f);
    ln_gate_kernel<<<Nn_NODES, 256>>>(nf, pRo, gam, bet, Wg, bg, h_out, pGate);

    // write path
    sgemm128<0><<<dim3(Ss / 128, Nn_NODES / 128), 256>>>(h_out, Wa, pA1, Nn_NODES, Ss, Dd, nullptr, 0.f);
    sgemm128<0><<<dim3(NPAD / 128, Nn_NODES / 128), 256>>>(pA1, pStT, pLog, Nn_NODES, NPAD, Ss, nullptr, 0.f);
    softmax_kernel<<<Nn_NODES / 8, dim3(32, 8)>>>(pLog, pGate, pWt);
    sgemm128<2><<<dim3(Ss / 128, Nn_NODES / 128), 256>>>(h_out, We, pEr, Nn_NODES, Ss, Dd, be, 0.f);
    sgemm128<3><<<dim3(Ss / 128, Nn_NODES / 128), 256>>>(h_out, Wc, pCo, Nn_NODES, Ss, Dd, bc, 0.f);
    aggregate_kernel<<<AGG_BLOCKS, 512>>>(pWt, pEr, pPE);
    aggregate_kernel<<<AGG_BLOCKS, 512>>>(pWt, pCo, pPW);
    finalize_kernel<<<(Kk_SLOTS * Ss + 255) / 256, 256>>>(state, ns_out);
}

// round 3
// speedup vs baseline: 2.3014x; 2.3014x over previous
#include <cuda_runtime.h>
#include <cuda_bf16.h>
#include <math.h>
#include <stdint.h>

#define Nn 65536
#define Dd 1024
#define Ss 512
#define Kslots 64
#define AGG_BLOCKS 256
#define AGG_ROWS (Nn / AGG_BLOCKS)

typedef __nv_bfloat16 bf16;

// ======================= helpers =============================================
__device__ __forceinline__ uint32_t smem_u32(const void* p) {
    uint32_t a;
    asm("{ .reg .u64 t; cvta.to.shared.u64 t, %1; cvt.u32.u64 %0, t; }" : "=r"(a) : "l"(p));
    return a;
}
__device__ __forceinline__ void cp16(uint32_t dst, const void* src) {
    asm volatile("cp.async.cg.shared.global [%0], [%1], 16;" :: "r"(dst), "l"(src));
}
__device__ __forceinline__ void ldsm4(uint32_t* r, uint32_t addr) {
    asm volatile("ldmatrix.sync.aligned.m8n8.x4.shared.b16 {%0,%1,%2,%3}, [%4];"
                 : "=r"(r[0]), "=r"(r[1]), "=r"(r[2]), "=r"(r[3]) : "r"(addr));
}
__device__ __forceinline__ void hmma(float* c, const uint32_t* a, const uint32_t* b) {
    asm volatile(
        "mma.sync.aligned.m16n8k16.row.col.f32.bf16.bf16.f32 "
        "{%0,%1,%2,%3}, {%4,%5,%6,%7}, {%8,%9}, {%0,%1,%2,%3};"
        : "+f"(c[0]), "+f"(c[1]), "+f"(c[2]), "+f"(c[3])
        : "r"(a[0]), "r"(a[1]), "r"(a[2]), "r"(a[3]), "r"(b[0]), "r"(b[1]));
}
__device__ __forceinline__ void split2(float x, bf16& h, bf16& l) {
    h = __float2bfloat16(x);
    l = __float2bfloat16(x - __bfloat162float(h));
}

// ======================= device global scratch ===============================
__device__ __align__(1024) bf16 g_xh[(size_t)Nn * Dd], g_xl[(size_t)Nn * Dd];
__device__ __align__(1024) bf16 g_qh[(size_t)Nn * Ss], g_ql[(size_t)Nn * Ss];
__device__ __align__(1024) bf16 g_ath[(size_t)Nn * Kslots], g_atl[(size_t)Nn * Kslots];
__device__ __align__(1024) bf16 g_rh[(size_t)Nn * Ss], g_rl[(size_t)Nn * Ss];
__device__ __align__(1024) bf16 g_hh[(size_t)Nn * Dd], g_hl[(size_t)Nn * Dd];
__device__ __align__(1024) float g_ro[(size_t)Nn * Dd];
__device__ __align__(1024) float g_logits[(size_t)Nn * Kslots];
__device__ __align__(1024) float g_erase[(size_t)Nn * Ss];
__device__ __align__(1024) float g_content[(size_t)Nn * Ss];
__device__ __align__(1024) float g_weighted[(size_t)Nn * Kslots];
__device__ float g_gate[Nn];
__device__ __align__(1024) float g_partE[(size_t)AGG_BLOCKS * Kslots * Ss];
__device__ __align__(1024) float g_partW[(size_t)AGG_BLOCKS * Kslots * Ss];
// weights transposed to [n,k] K-major, bf16 hi/lo planes
__device__ __align__(1024) bf16 g_wqT[2][(size_t)Ss * Dd];
__device__ __align__(1024) bf16 g_woT[2][(size_t)Dd * Ss];
__device__ __align__(1024) bf16 g_waT[2][(size_t)Ss * Dd];
__device__ __align__(1024) bf16 g_weT[2][(size_t)Ss * Dd];
__device__ __align__(1024) bf16 g_wcT[2][(size_t)Ss * Dd];
__device__ __align__(1024) bf16 g_kp[2][(size_t)Kslots * Ss];   // Kp  [64,512]
__device__ __align__(1024) bf16 g_vT[2][(size_t)Ss * Kslots];   // V^T [512,64]
__device__ __align__(1024) bf16 g_st[2][(size_t)Kslots * Ss];   // state [64,512]

// ======================= mma.sync bf16 split GEMM ============================
// C[M,Nc] = act( (Ah+Al) @ (Bh+Bl)^T );  A,B stored [rows,K] K-major.
// 3-term: Ah*Bh + Ah*Bl + Al*Bh, fp32 accumulate in registers.
// MODE: 0 fp32, 1 fp32*scale, 2 sigmoid(x+bias), 3 tanh(x+bias), 4 split bf16 out
template <int BM, int BN, int MODE>
__global__ void __launch_bounds__(256, 1)
mgemm(const bf16* __restrict__ Ah, const bf16* __restrict__ Al,
      const bf16* __restrict__ Bh, const bf16* __restrict__ Bl,
      int Kd, int Nc,
      float* __restrict__ Cf, bf16* __restrict__ Chi, bf16* __restrict__ Clo,
      const float* __restrict__ bias, float scale)
{
    constexpr int NWN = (BN >= 128) ? 4 : 2;
    constexpr int NWM = 8 / NWN;
    constexpr int WM = BM / NWM;      // 64 or 32
    constexpr int MF = WM / 16;       // 4 or 2
    constexpr int APL = BM * 128;     // bytes per A plane per stage (KC=64 bf16 = 128B row)
    constexpr int BPL = BN * 128;
    constexpr int STAGE = 2 * APL + 2 * BPL;
    constexpr int SEGS = (2 * BM + 2 * BN) * 8;
    constexpr int SPT = SEGS / 256;

    extern __shared__ char smem_raw[];
    uint32_t sb0 = smem_u32(smem_raw);

    int tid = threadIdx.x, w = tid >> 5, lane = tid & 31;
    int row0 = blockIdx.y * BM, col0 = blockIdx.x * BN;
    int wm0 = (w / NWN) * WM, wn0 = (w % NWN) * 32;
    int nch = Kd >> 6;

    float acc[MF][4][4];
#pragma unroll
    for (int i = 0; i < MF; i++)
#pragma unroll
        for (int j = 0; j < 4; j++)
#pragma unroll
            for (int u = 0; u < 4; u++) acc[i][j][u] = 0.f;

    // ---- stage loader ----
    auto issue = [&](int c) {
        uint32_t sbase = sb0 + (c & 1) * STAGE;
        int k0 = c << 6;
#pragma unroll
        for (int i = 0; i < SPT; i++) {
            int sg = i * 256 + tid;
            int rr = sg >> 3, q = sg & 7;
            const bf16* srcp;
            uint32_t dstb;
            int lr;
            if (rr < 2 * BM) {
                int pl = rr >= BM;
                lr = rr - pl * BM;
                srcp = (pl ? Al : Ah) + (size_t)(row0 + lr) * Kd + k0 + q * 8;
                dstb = sbase + pl * APL;
            } else {
                int rr2 = rr - 2 * BM;
                int pl = rr2 >= BN;
                lr = rr2 - pl * BN;
                srcp = (pl ? Bl : Bh) + (size_t)(col0 + lr) * Kd + k0 + q * 8;
                dstb = sbase + 2 * APL + pl * BPL;
            }
            uint32_t off = (uint32_t)(lr * 128 + q * 16);
            off ^= (off >> 3) & 0x70;
            cp16(dstb + off, (const void*)srcp);
        }
        asm volatile("cp.async.commit_group;");
    };

    issue(0);
    for (int c = 0; c < nch; c++) {
        if (c + 1 < nch) {
            issue(c + 1);
            asm volatile("cp.async.wait_group 1;");
        } else {
            asm volatile("cp.async.wait_group 0;");
        }
        __syncthreads();

        uint32_t sA = sb0 + (c & 1) * STAGE;
        uint32_t sAl = sA + APL, sBh = sA + 2 * APL, sBl = sBh + BPL;
#pragma unroll
        for (int ks = 0; ks < 4; ks++) {
            uint32_t ah[MF][4], al_[MF][4];
#pragma unroll
            for (int i = 0; i < MF; i++) {
                uint32_t off = (uint32_t)((wm0 + i * 16 + (lane & 15)) * 128 +
                                          ks * 32 + ((lane >> 4) << 4));
                off ^= (off >> 3) & 0x70;
                ldsm4(ah[i], sA + off);
                ldsm4(al_[i], sAl + off);
            }
            uint32_t bh[4][2], bl[4][2];
#pragma unroll
            for (int j2 = 0; j2 < 2; j2++) {
                uint32_t off = (uint32_t)((wn0 + j2 * 16 + (lane & 7) + ((lane >> 4) << 3)) * 128 +
                                          ks * 32 + (((lane >> 3) & 1) << 4));
                off ^= (off >> 3) & 0x70;
                uint32_t t[4];
                ldsm4(t, sBh + off);
                bh[2 * j2][0] = t[0]; bh[2 * j2][1] = t[1];
                bh[2 * j2 + 1][0] = t[2]; bh[2 * j2 + 1][1] = t[3];
                ldsm4(t, sBl + off);
                bl[2 * j2][0] = t[0]; bl[2 * j2][1] = t[1];
                bl[2 * j2 + 1][0] = t[2]; bl[2 * j2 + 1][1] = t[3];
            }
#pragma unroll
            for (int i = 0; i < MF; i++)
#pragma unroll
                for (int j = 0; j < 4; j++) hmma(acc[i][j], ah[i], bh[j]);
#pragma unroll
            for (int i = 0; i < MF; i++)
#pragma unroll
                for (int j = 0; j < 4; j++) hmma(acc[i][j], ah[i], bl[j]);
#pragma unroll
            for (int i = 0; i < MF; i++)
#pragma unroll
                for (int j = 0; j < 4; j++) hmma(acc[i][j], al_[i], bh[j]);
        }
        __syncthreads();
    }

    // ---- epilogue ----
#pragma unroll
    for (int i = 0; i < MF; i++) {
#pragma unroll
        for (int j = 0; j < 4; j++) {
            int r = row0 + wm0 + i * 16 + (lane >> 2);
            int cp = col0 + wn0 + j * 8 + ((lane & 3) << 1);
#pragma unroll
            for (int half = 0; half < 2; half++) {
                int rr = r + half * 8;
                float x0 = acc[i][j][half * 2 + 0];
                float x1 = acc[i][j][half * 2 + 1];
                if (MODE == 4) {
                    bf16 h0, l0, h1, l1;
                    split2(x0, h0, l0);
                    split2(x1, h1, l1);
                    __nv_bfloat162 ph; ph.x = h0; ph.y = h1;
                    __nv_bfloat162 pl2; pl2.x = l0; pl2.y = l1;
                    *reinterpret_cast<__nv_bfloat162*>(&Chi[(size_t)rr * Nc + cp]) = ph;
                    *reinterpret_cast<__nv_bfloat162*>(&Clo[(size_t)rr * Nc + cp]) = pl2;
                } else {
                    if (MODE == 1) { x0 *= scale; x1 *= scale; }
                    if (MODE == 2) {
                        x0 = 1.f / (1.f + __expf(-(x0 + bias[cp])));
                        x1 = 1.f / (1.f + __expf(-(x1 + bias[cp + 1])));
                    }
                    if (MODE == 3) {
                        x0 = tanhf(x0 + bias[cp]);
                        x1 = tanhf(x1 + bias[cp + 1]);
                    }
                    float2 o; o.x = x0; o.y = x1;
                    *reinterpret_cast<float2*>(&Cf[(size_t)rr * Nc + cp]) = o;
                }
            }
        }
    }
}

// ======================= prep / elementwise kernels ==========================
__global__ void convert_split_kernel(const float* __restrict__ in,
                                     bf16* __restrict__ oh, bf16* __restrict__ ol,
                                     size_t n4) {
    size_t i = (size_t)blockIdx.x * blockDim.x + threadIdx.x;
    if (i >= n4) return;
    float4 v = reinterpret_cast<const float4*>(in)[i];
    bf16 h0, l0, h1, l1, h2, l2, h3, l3;
    split2(v.x, h0, l0); split2(v.y, h1, l1); split2(v.z, h2, l2); split2(v.w, h3, l3);
    __nv_bfloat162 a, b, c, d;
    a.x = h0; a.y = h1; b.x = h2; b.y = h3;
    c.x = l0; c.y = l1; d.x = l2; d.y = l3;
    reinterpret_cast<__nv_bfloat162*>(oh)[i * 2] = a;
    reinterpret_cast<__nv_bfloat162*>(oh)[i * 2 + 1] = b;
    reinterpret_cast<__nv_bfloat162*>(ol)[i * 2] = c;
    reinterpret_cast<__nv_bfloat162*>(ol)[i * 2 + 1] = d;
}

__global__ void transpose_split_kernel(const float* __restrict__ W,
                                       bf16* __restrict__ Th, bf16* __restrict__ Tl,
                                       int R, int C) {
    __shared__ float t[32][33];
    int c0 = blockIdx.x * 32, r0 = blockIdx.y * 32;
    int tx = threadIdx.x, ty = threadIdx.y;
#pragma unroll
    for (int i = 0; i < 32; i += 8)
        t[ty + i][tx] = W[(size_t)(r0 + ty + i) * C + c0 + tx];
    __syncthreads();
#pragma unroll
    for (int i = 0; i < 32; i += 8) {
        float v = t[tx][ty + i];
        bf16 h, l;
        split2(v, h, l);
        size_t idx = (size_t)(c0 + ty + i) * R + r0 + tx;
        Th[idx] = h;
        Tl[idx] = l;
    }
}

__global__ void kv_kernel(const float* __restrict__ state,
                          const float* __restrict__ Wk,
                          const float* __restrict__ Wv) {
    int j = blockIdx.x;
    __shared__ float srow[Ss];
    for (int c = threadIdx.x; c < Ss; c += blockDim.x) srow[c] = state[j * Ss + c];
    __syncthreads();
    for (int c = threadIdx.x; c < Ss; c += blockDim.x) {
        float ak = 0.f, av = 0.f;
        for (int t = 0; t < Ss; t++) {
            float s = srow[t];
            ak += s * Wk[t * Ss + c];
            av += s * Wv[t * Ss + c];
        }
        bf16 h, l;
        split2(ak, h, l);
        g_kp[0][j * Ss + c] = h; g_kp[1][j * Ss + c] = l;
        split2(av, h, l);
        g_vT[0][c * Kslots + j] = h; g_vT[1][c * Kslots + j] = l;
        split2(srow[c], h, l);
        g_st[0][j * Ss + c] = h; g_st[1][j * Ss + c] = l;
    }
}

template <bool SPLIT_OUT>
__global__ void softmax_kernel(const float* __restrict__ logits,
                               const float* __restrict__ gate,
                               bf16* __restrict__ oh, bf16* __restrict__ ol,
                               float* __restrict__ of) {
    int row = blockIdx.x * blockDim.y + threadIdx.y;
    int lane = threadIdx.x;
    float v0 = logits[(size_t)row * 64 + lane];
    float v1 = logits[(size_t)row * 64 + 32 + lane];
    float m = fmaxf(v0, v1);
#pragma unroll
    for (int o = 16; o; o >>= 1) m = fmaxf(m, __shfl_xor_sync(0xffffffffu, m, o));
    float e0 = __expf(v0 - m), e1 = __expf(v1 - m);
    float s = e0 + e1;
#pragma unroll
    for (int o = 16; o; o >>= 1) s += __shfl_xor_sync(0xffffffffu, s, o);
    float inv = 1.f / s;
    if (!SPLIT_OUT) inv *= gate[row];
    float a0 = e0 * inv, a1 = e1 * inv;
    if (SPLIT_OUT) {
        bf16 h, l;
        split2(a0, h, l);
        oh[(size_t)row * 64 + lane] = h; ol[(size_t)row * 64 + lane] = l;
        split2(a1, h, l);
        oh[(size_t)row * 64 + 32 + lane] = h; ol[(size_t)row * 64 + 32 + lane] = l;
    } else {
        of[(size_t)row * 64 + lane] = a0;
        of[(size_t)row * 64 + 32 + lane] = a1;
    }
}

__global__ void ln_gate_kernel(const float* __restrict__ nf,
                               const float* __restrict__ ro,
                               const float* __restrict__ gamma,
                               const float* __restrict__ beta,
                               const float* __restrict__ Wg,
                               const float* __restrict__ bg,
                               float* __restrict__ h,
                               bf16* __restrict__ hh, bf16* __restrict__ hl,
                               float* __restrict__ gate) {
    int row = blockIdx.x;
    int tid = threadIdx.x;
    __shared__ float sh[16];
    float4 a = reinterpret_cast<const float4*>(nf + (size_t)row * Dd)[tid];
    float4 b = reinterpret_cast<const float4*>(ro + (size_t)row * Dd)[tid];
    float v0 = a.x + b.x, v1 = a.y + b.y, v2 = a.z + b.z, v3 = a.w + b.w;
    float s = v0 + v1 + v2 + v3;
    float sq = v0 * v0 + v1 * v1 + v2 * v2 + v3 * v3;
    int lane = tid & 31, wid = tid >> 5;
#pragma unroll
    for (int o = 16; o; o >>= 1) {
        s += __shfl_xor_sync(0xffffffffu, s, o);
        sq += __shfl_xor_sync(0xffffffffu, sq, o);
    }
    if (lane == 0) { sh[wid] = s; sh[8 + wid] = sq; }
    __syncthreads();
    if (tid < 32) {
        float rs = (lane < 8) ? sh[lane] : 0.f;
        float rq = (lane < 8) ? sh[8 + lane] : 0.f;
#pragma unroll
        for (int o = 4; o; o >>= 1) {
            rs += __shfl_xor_sync(0xffffffffu, rs, o);
            rq += __shfl_xor_sync(0xffffffffu, rq, o);
        }
        if (lane == 0) { sh[0] = rs; sh[1] = rq; }
    }
    __syncthreads();
    float mu = sh[0] * (1.f / Dd);
    float var = sh[1] * (1.f / Dd) - mu * mu;
    float inv = rsqrtf(var + 1e-6f);
    __syncthreads();

    float4 g4 = reinterpret_cast<const float4*>(gamma)[tid];
    float4 b4 = reinterpret_cast<const float4*>(beta)[tid];
    float h0 = (v0 - mu) * inv * g4.x + b4.x;
    float h1 = (v1 - mu) * inv * g4.y + b4.y;
    float h2 = (v2 - mu) * inv * g4.z + b4.z;
    float h3 = (v3 - mu) * inv * g4.w + b4.w;
    float4 o4; o4.x = h0; o4.y = h1; o4.z = h2; o4.w = h3;
    reinterpret_cast<float4*>(h + (size_t)row * Dd)[tid] = o4;

    bf16 th0, tl0, th1, tl1, th2, tl2, th3, tl3;
    split2(h0, th0, tl0); split2(h1, th1, tl1);
    split2(h2, th2, tl2); split2(h3, th3, tl3);
    __nv_bfloat162 p0, p1, q0, q1;
    p0.x = th0; p0.y = th1; p1.x = th2; p1.y = th3;
    q0.x = tl0; q0.y = tl1; q1.x = tl2; q1.y = tl3;
    reinterpret_cast<__nv_bfloat162*>(hh + (size_t)row * Dd)[tid * 2] = p0;
    reinterpret_cast<__nv_bfloat162*>(hh + (size_t)row * Dd)[tid * 2 + 1] = p1;
    reinterpret_cast<__nv_bfloat162*>(hl + (size_t)row * Dd)[tid * 2] = q0;
    reinterpret_cast<__nv_bfloat162*>(hl + (size_t)row * Dd)[tid * 2 + 1] = q1;

    float4 w4 = reinterpret_cast<const float4*>(Wg)[tid];
    float gd = h0 * w4.x + h1 * w4.y + h2 * w4.z + h3 * w4.w;
#pragma unroll
    for (int o = 16; o; o >>= 1) gd += __shfl_xor_sync(0xffffffffu, gd, o);
    if (lane == 0) sh[wid] = gd;
    __syncthreads();
    if (tid == 0) {
        float t = 0.f;
#pragma unroll
        for (int wv = 0; wv < 8; wv++) t += sh[wv];
        gate[row] = 1.f / (1.f + __expf(-(t + bg[0])));
    }
}

__global__ void __launch_bounds__(512)
aggregate_kernel(const float* __restrict__ w, const float* __restrict__ vec,
                 float* __restrict__ part) {
    int blk = blockIdx.x;
    int tid = threadIdx.x;
    int j = tid >> 3;
    int sb = tid & 7;
    float acc[64];
#pragma unroll
    for (int t = 0; t < 64; t++) acc[t] = 0.f;
    __shared__ float ws[64];
    __shared__ float vs[Ss];
    int r0 = blk * AGG_ROWS;
    for (int r = 0; r < AGG_ROWS; r++) {
        size_t row = r0 + r;
        __syncthreads();
        if (tid < 64) ws[tid] = w[row * 64 + tid];
        if (tid < 512) vs[tid] = vec[row * Ss + tid];
        __syncthreads();
        float wv = ws[j];
#pragma unroll
        for (int t = 0; t < 64; t++) acc[t] += wv * vs[sb + 8 * t];
    }
    float* p = part + (size_t)blk * (Kslots * Ss) + j * Ss;
#pragma unroll
    for (int t = 0; t < 64; t++) p[sb + 8 * t] = acc[t];
}

__global__ void finalize_kernel(const float* __restrict__ state, float* __restrict__ out) {
    int e = blockIdx.x * blockDim.x + threadIdx.x;
    if (e >= Kslots * Ss) return;
    float se = 0.f, sw = 0.f;
    for (int r = 0; r < AGG_BLOCKS; r++) {
        se += g_partE[(size_t)r * (Kslots * Ss) + e];
        sw += g_partW[(size_t)r * (Kslots * Ss) + e];
    }
    float ea = fminf(fmaxf(se, 0.f), 1.f);
    out[e] = state[e] * (1.f - ea) + sw;
}

// ======================= launcher ============================================
extern "C" void kernel_launch(void* const* d_in, const int* in_sizes, int n_in,
                              void* d_out, int out_size) {
    const float* nf    = (const float*)d_in[0];
    const float* state = (const float*)d_in[1];
    const float* Wq    = (const float*)d_in[2];
    const float* Wk    = (const float*)d_in[3];
    const float* Wv    = (const float*)d_in[4];
    const float* Wo    = (const float*)d_in[5];
    const float* gam   = (const float*)d_in[6];
    const float* bet   = (const float*)d_in[7];
    const float* Wa    = (const float*)d_in[8];
    const float* Wg    = (const float*)d_in[9];
    const float* bg    = (const float*)d_in[10];
    const float* We    = (const float*)d_in[11];
    const float* be    = (const float*)d_in[12];
    const float* Wc    = (const float*)d_in[13];
    const float* bc    = (const float*)d_in[14];

    float* h_out  = (float*)d_out;
    float* ns_out = (float*)d_out + (size_t)Nn * Dd;

    auto sym = [](const void* s) {
        void* p = nullptr;
        cudaGetSymbolAddress(&p, s);
        return p;
    };
    bf16* xh  = (bf16*)sym(g_xh);
    bf16* xl  = (bf16*)sym(g_xl);
    bf16* qh  = (bf16*)sym(g_qh);
    bf16* ql  = (bf16*)sym(g_ql);
    bf16* ath = (bf16*)sym(g_ath);
    bf16* atl = (bf16*)sym(g_atl);
    bf16* rh  = (bf16*)sym(g_rh);
    bf16* rl  = (bf16*)sym(g_rl);
    bf16* hh  = (bf16*)sym(g_hh);
    bf16* hl  = (bf16*)sym(g_hl);
    float* ro    = (float*)sym(g_ro);
    float* logit = (float*)sym(g_logits);
    float* ers   = (float*)sym(g_erase);
    float* cnt   = (float*)sym(g_content);
    float* wtd   = (float*)sym(g_weighted);
    float* gate  = (float*)sym(g_gate);
    float* pE    = (float*)sym(g_partE);
    float* pW    = (float*)sym(g_partW);
    bf16* wqT = (bf16*)sym(g_wqT);
    bf16* woT = (bf16*)sym(g_woT);
    bf16* waT = (bf16*)sym(g_waT);
    bf16* weT = (bf16*)sym(g_weT);
    bf16* wcT = (bf16*)sym(g_wcT);
    bf16* kp  = (bf16*)sym(g_kp);
    bf16* vT  = (bf16*)sym(g_vT);
    bf16* st  = (bf16*)sym(g_st);
    const size_t SD = (size_t)Ss * Dd;
    const size_t DS = (size_t)Dd * Ss;
    const size_t KS = (size_t)Kslots * Ss;
    const size_t SK = (size_t)Ss * Kslots;

    const int SM_BIG   = 2 * (2 * 128 * 128 + 2 * 128 * 128);   // 131072
    const int SM_SMALL = 2 * (2 * 128 * 128 + 2 * 64 * 128);    //  98304
    cudaFuncSetAttribute(mgemm<128, 128, 0>, cudaFuncAttributeMaxDynamicSharedMemorySize, SM_BIG);
    cudaFuncSetAttribute(mgemm<128, 128, 2>, cudaFuncAttributeMaxDynamicSharedMemorySize, SM_BIG);
    cudaFuncSetAttribute(mgemm<128, 128, 3>, cudaFuncAttributeMaxDynamicSharedMemorySize, SM_BIG);
    cudaFuncSetAttribute(mgemm<128, 128, 4>, cudaFuncAttributeMaxDynamicSharedMemorySize, SM_BIG);
    cudaFuncSetAttribute(mgemm<128, 64, 0>, cudaFuncAttributeMaxDynamicSharedMemorySize, SM_SMALL);
    cudaFuncSetAttribute(mgemm<128, 64, 1>, cudaFuncAttributeMaxDynamicSharedMemorySize, SM_SMALL);

    const float scale = 0.044194173824159216f;  // 1/sqrt(512)

    // ---- prep ----
    convert_split_kernel<<<(Nn * (Dd / 4)) / 256, 256>>>(nf, xh, xl, (size_t)Nn * Dd / 4);
    transpose_split_kernel<<<dim3(Ss / 32, Dd / 32), dim3(32, 8)>>>(Wq, wqT, wqT + SD, Dd, Ss);
    transpose_split_kernel<<<dim3(Dd / 32, Ss / 32), dim3(32, 8)>>>(Wo, woT, woT + DS, Ss, Dd);
    transpose_split_kernel<<<dim3(Ss / 32, Dd / 32), dim3(32, 8)>>>(Wa, waT, waT + SD, Dd, Ss);
    transpose_split_kernel<<<dim3(Ss / 32, Dd / 32), dim3(32, 8)>>>(We, weT, weT + SD, Dd, Ss);
    transpose_split_kernel<<<dim3(Ss / 32, Dd / 32), dim3(32, 8)>>>(Wc, wcT, wcT + SD, Dd, Ss);
    kv_kernel<<<Kslots, 256>>>(state, Wk, Wv);

    // ---- read path ----
    mgemm<128, 128, 4><<<dim3(4, 512), 256, SM_BIG>>>(xh, xl, wqT, wqT + SD, Dd, Ss,
                                                      nullptr, qh, ql, nullptr, 0.f);
    mgemm<128, 64, 1><<<dim3(1, 512), 256, SM_SMALL>>>(qh, ql, kp, kp + KS, Ss, 64,
                                                       logit, nullptr, nullptr, nullptr, scale);
    softmax_kernel<true><<<Nn / 8, dim3(32, 8)>>>(logit, nullptr, ath, atl, nullptr);
    mgemm<128, 128, 4><<<dim3(4, 512), 256, SM_BIG>>>(ath, atl, vT, vT + SK, Kslots, Ss,
                                                      nullptr, rh, rl, nullptr, 0.f);
    mgemm<128, 128, 0><<<dim3(8, 512), 256, SM_BIG>>>(rh, rl, woT, woT + DS, Ss, Dd,
                                                      ro, nullptr, nullptr, nullptr, 0.f);
    ln_gate_kernel<<<Nn, 256>>>(nf, ro, gam, bet, Wg, bg, h_out, hh, hl, gate);

    // ---- write path ----
    mgemm<128, 128, 4><<<dim3(4, 512), 256, SM_BIG>>>(hh, hl, waT, waT + SD, Dd, Ss,
                                                      nullptr, qh, ql, nullptr, 0.f);
    mgemm<128, 64, 0><<<dim3(1, 512), 256, SM_SMALL>>>(qh, ql, st, st + KS, Ss, 64,
                                                       logit, nullptr, nullptr, nullptr, 0.f);
    softmax_kernel<false><<<Nn / 8, dim3(32, 8)>>>(logit, gate, nullptr, nullptr, wtd);
    mgemm<128, 128, 2><<<dim3(4, 512), 256, SM_BIG>>>(hh, hl, weT, weT + SD, Dd, Ss,
                                                      ers, nullptr, nullptr, be, 0.f);
    mgemm<128, 128, 3><<<dim3(4, 512), 256, SM_BIG>>>(hh, hl, wcT, wcT + SD, Dd, Ss,
                                                      cnt, nullptr, nullptr, bc, 0.f);
    aggregate_kernel<<<AGG_BLOCKS, 512>>>(wtd, ers, pE);
    aggregate_kernel<<<AGG_BLOCKS, 512>>>(wtd, cnt, pW);
    finalize_kernel<<<(Kslots * Ss + 255) / 256, 256>>>(state, ns_out);
}